// round 12
// baseline (speedup 1.0000x reference)
#include <cuda_runtime.h>
#include <cuda_fp16.h>

#define NN 100000
#define NE 1600000
#define F_HID 128
#define F_CLS 64
#define GB1M ((NN + 127) / 128)    // 128-row mma tile blocks = 782
#define ASTRIDE 136                // halfs per smem row (272B, LDSM conflict-free)
#define BSTRIDE 72                 // halfs per smem row for 64-wide W2 (144B)

#define NB_F 296                   // fused CSR kernel: 2 blocks/SM on 148 SMs
#define TPB_F 512
#define SCAN_BLKS 196              // ceil(NN/512)

// ---- scratch (device globals; no allocs allowed) ----
// g_cnt layout: [0,NN)=cnt_in, [NN,2NN)=cnt_out, [2NN,2NN+256)=scan totals
__device__ int    g_cnt[2 * NN + 256];
__device__ int    g_row_ptr[NN + 1];
__device__ int    g_epos[NE];       // edge position within its dst row
__device__ int    g_csr_src[NE];
__device__ float  g_norm_in[NN];
__device__ float  g_norm_out[NN];
__device__ __half g_t1[(size_t)NN * F_HID];
__device__ __half g_h [(size_t)NN * F_HID];
__device__ __half g_t2[(size_t)NN * F_CLS];

// software grid barrier state (self-resetting; gen is monotonic)
__device__ unsigned g_bar_cnt;
__device__ volatile unsigned g_bar_gen;

#define CNT_IN   (g_cnt)
#define CNT_OUT  (g_cnt + NN)
#define SCAN_VAL (g_cnt + 2 * NN)

// ---- fp16 vector load helpers ----
__device__ __forceinline__ void ldg_h4_f(const __half* p, float2& lo, float2& hi) {
    uint2 raw = __ldg((const uint2*)p);
    lo = __half22float2(*(const __half2*)&raw.x);
    hi = __half22float2(*(const __half2*)&raw.y);
}
__device__ __forceinline__ float2 ldg_h2_f(const __half* p) {
    unsigned int raw = __ldg((const unsigned int*)p);
    return __half22float2(*(const __half2*)&raw);
}

__device__ __forceinline__ int warp_incl_scan(int x, int lane) {
#pragma unroll
    for (int o = 1; o < 32; o <<= 1) {
        int y = __shfl_up_sync(0xffffffffu, x, o);
        if (lane >= o) x += y;
    }
    return x;
}

__device__ __forceinline__ void grid_bar() {
    __syncthreads();
    if (threadIdx.x == 0) {
        unsigned gen = g_bar_gen;
        __threadfence();
        if (atomicAdd(&g_bar_cnt, 1u) == NB_F - 1) {
            g_bar_cnt = 0;
            __threadfence();
            g_bar_gen = gen + 1;
        } else {
            while (g_bar_gen == gen) { }
            __threadfence();
        }
    }
    __syncthreads();
}

// ===========================================================================
// Fused CSR build: zero -> count(+epos) -> scan -> norms/row_ptr -> fill
// One launch, software grid barriers. All NB_F blocks resident by
// __launch_bounds__(TPB_F, 2) with NB_F = 2*148.
// ===========================================================================
__global__ __launch_bounds__(TPB_F, 2)
void csr_build_fused(const int4* __restrict__ src4,
                     const int4* __restrict__ dst4) {
    const int tid = threadIdx.x;
    const int bid = blockIdx.x;
    const int gtid = bid * TPB_F + tid;
    const int gstride = NB_F * TPB_F;
    const int lane = tid & 31, wid = tid >> 5;

    __shared__ int ws[16];
    __shared__ int s_base;

    // P0: zero the counters (2*NN ints = 50000 int4)
    for (int i = gtid; i < (2 * NN) / 4; i += gstride)
        ((int4*)g_cnt)[i] = make_int4(0, 0, 0, 0);
    grid_bar();

    // P1: degree counts; atomic return = edge position within dst row
    for (int i = gtid; i < NE / 4; i += gstride) {
        int4 s = __ldg(src4 + i);
        int4 d = __ldg(dst4 + i);
        atomicAdd(&CNT_OUT[s.x], 1); atomicAdd(&CNT_OUT[s.y], 1);
        atomicAdd(&CNT_OUT[s.z], 1); atomicAdd(&CNT_OUT[s.w], 1);
        int4 p;
        p.x = atomicAdd(&CNT_IN[d.x], 1);
        p.y = atomicAdd(&CNT_IN[d.y], 1);
        p.z = atomicAdd(&CNT_IN[d.z], 1);
        p.w = atomicAdd(&CNT_IN[d.w], 1);
        ((int4*)g_epos)[i] = p;
    }
    grid_bar();

    // P2a: per-block inclusive scan of 512 counts (blocks [0, SCAN_BLKS))
    int v = 0, incl = 0;
    const int i2 = bid * TPB_F + tid;
    if (bid < SCAN_BLKS) {
        v = (i2 < NN) ? CNT_IN[i2] : 0;
        int x = warp_incl_scan(v, lane);
        if (lane == 31) ws[wid] = x;
        __syncthreads();
        if (wid == 0) {
            int y = (lane < 16) ? ws[lane] : 0;
            y = warp_incl_scan(y, lane);
            if (lane < 16) ws[lane] = y;
        }
        __syncthreads();
        incl = x + (wid ? ws[wid - 1] : 0);
        if (tid == 0) SCAN_VAL[bid] = ws[15];
    }
    grid_bar();

    // P2b: cross-block exclusive prefix + write row_ptr / norms
    if (bid < SCAN_BLKS) {
        if (tid == 0) s_base = 0;
        __syncthreads();
        if (tid < bid) atomicAdd(&s_base, SCAN_VAL[tid]);
        __syncthreads();
        if (i2 < NN) {
            g_row_ptr[i2] = s_base + incl - v;
            g_norm_in[i2]  = rsqrtf(fmaxf((float)v, 1.0f));
            g_norm_out[i2] = rsqrtf(fmaxf((float)CNT_OUT[i2], 1.0f));
        }
        if (bid == 0 && tid == 0) g_row_ptr[NN] = NE;
    }
    grid_bar();

    // P3: fill CSR (pure scatter, no atomics)
    for (int i = gtid; i < NE / 4; i += gstride) {
        int4 s = __ldg(src4 + i);
        int4 d = __ldg(dst4 + i);
        int4 p = ((const int4*)g_epos)[i];
        g_csr_src[__ldg(g_row_ptr + d.x) + p.x] = s.x;
        g_csr_src[__ldg(g_row_ptr + d.y) + p.y] = s.y;
        g_csr_src[__ldg(g_row_ptr + d.z) + p.z] = s.z;
        g_csr_src[__ldg(g_row_ptr + d.w) + p.w] = s.w;
    }
}

// ===========================================================================
// gemm1 (HMMA fp16, fp32 accum):
//   t1[row] = half( (x[row] @ W1) * norm_out[row] )
// ===========================================================================
__global__ __launch_bounds__(256)
void gemm1_mma_kernel(const float* __restrict__ X,
                      const float* __restrict__ W,
                      __half* __restrict__ Y) {
    extern __shared__ __half hsm[];
    __half* A_s = hsm;                    // [128][ASTRIDE]
    __half* B_s = hsm + 128 * ASTRIDE;    // [128][ASTRIDE]

    const int tid = threadIdx.x;
    const int row0 = blockIdx.x * 128;

    for (int i = tid; i < 128 * 32; i += 256) {
        int k = i >> 5, c4 = i & 31;
        float4 v = __ldg(((const float4*)W) + i);
        __half2 h01 = __floats2half2_rn(v.x, v.y);
        __half2 h23 = __floats2half2_rn(v.z, v.w);
        uint2 u = make_uint2(*(unsigned*)&h01, *(unsigned*)&h23);
        *((uint2*)(B_s + k * ASTRIDE + c4 * 4)) = u;
    }
    for (int i = tid; i < 128 * 32; i += 256) {
        int r = i >> 5, c4 = i & 31;
        int row = row0 + r;
        float4 v = (row < NN)
            ? __ldg(((const float4*)(X + (size_t)row * 128)) + c4)
            : make_float4(0.f, 0.f, 0.f, 0.f);
        __half2 h01 = __floats2half2_rn(v.x, v.y);
        __half2 h23 = __floats2half2_rn(v.z, v.w);
        uint2 u = make_uint2(*(unsigned*)&h01, *(unsigned*)&h23);
        *((uint2*)(A_s + r * ASTRIDE + c4 * 4)) = u;
    }
    __syncthreads();

    const int w = tid >> 5, lane = tid & 31;
    const int mrow = w * 16;

    float acc[16][4];
#pragma unroll
    for (int t = 0; t < 16; t++)
#pragma unroll
        for (int j = 0; j < 4; j++) acc[t][j] = 0.f;

#pragma unroll
    for (int ks = 0; ks < 8; ks++) {
        const int k0 = ks * 16;
        unsigned a0, a1, a2, a3;
        {
            const __half* pa = A_s + (mrow + (lane & 15)) * ASTRIDE
                             + k0 + (lane >> 4) * 8;
            unsigned addr = (unsigned)__cvta_generic_to_shared(pa);
            asm volatile("ldmatrix.sync.aligned.m8n8.x4.shared.b16 "
                         "{%0,%1,%2,%3}, [%4];"
                         : "=r"(a0), "=r"(a1), "=r"(a2), "=r"(a3) : "r"(addr));
        }
#pragma unroll
        for (int nt = 0; nt < 8; nt++) {
            unsigned b0, b1, b2, b3;
            const __half* pb = B_s + (k0 + (lane & 15)) * ASTRIDE
                             + nt * 16 + (lane >> 4) * 8;
            unsigned addr = (unsigned)__cvta_generic_to_shared(pb);
            asm volatile("ldmatrix.sync.aligned.m8n8.x4.trans.shared.b16 "
                         "{%0,%1,%2,%3}, [%4];"
                         : "=r"(b0), "=r"(b1), "=r"(b2), "=r"(b3) : "r"(addr));
            asm volatile("mma.sync.aligned.m16n8k16.row.col.f32.f16.f16.f32 "
                         "{%0,%1,%2,%3},{%4,%5,%6,%7},{%8,%9},{%0,%1,%2,%3};"
                         : "+f"(acc[nt*2][0]), "+f"(acc[nt*2][1]),
                           "+f"(acc[nt*2][2]), "+f"(acc[nt*2][3])
                         : "r"(a0), "r"(a1), "r"(a2), "r"(a3),
                           "r"(b0), "r"(b1));
            asm volatile("mma.sync.aligned.m16n8k16.row.col.f32.f16.f16.f32 "
                         "{%0,%1,%2,%3},{%4,%5,%6,%7},{%8,%9},{%0,%1,%2,%3};"
                         : "+f"(acc[nt*2+1][0]), "+f"(acc[nt*2+1][1]),
                           "+f"(acc[nt*2+1][2]), "+f"(acc[nt*2+1][3])
                         : "r"(a0), "r"(a1), "r"(a2), "r"(a3),
                           "r"(b2), "r"(b3));
        }
    }

    const int ra = row0 + mrow + (lane >> 2);
    const int rb = ra + 8;
    const float nsa = (ra < NN) ? __ldg(g_norm_out + ra) : 0.f;
    const float nsb = (rb < NN) ? __ldg(g_norm_out + rb) : 0.f;
    const int cbase = (lane & 3) * 2;
#pragma unroll
    for (int t = 0; t < 16; t++) {
        int c = t * 8 + cbase;
        if (ra < NN) {
            __half2 h = __floats2half2_rn(acc[t][0] * nsa, acc[t][1] * nsa);
            *((__half2*)(Y + (size_t)ra * 128 + c)) = h;
        }
        if (rb < NN) {
            __half2 h = __floats2half2_rn(acc[t][2] * nsb, acc[t][3] * nsb);
            *((__half2*)(Y + (size_t)rb * 128 + c)) = h;
        }
    }
}

// ===========================================================================
// gather128+relu: h[n] = half( relu(norm_in[n]*sum t1[csr] + b1) )
// ===========================================================================
__global__ __launch_bounds__(256)
void gather128_relu_kernel(const __half* __restrict__ T,
                           const float* __restrict__ b,
                           __half* __restrict__ out) {
    int w = (blockIdx.x * blockDim.x + threadIdx.x) >> 5;
    int lane = threadIdx.x & 31;
    if (w >= NN) return;
    int beg = g_row_ptr[w], end = g_row_ptr[w + 1];
    float4 acc = make_float4(0.f, 0.f, 0.f, 0.f);
    int i = beg;
    for (; i + 3 < end; i += 4) {
        int s0 = __ldg(g_csr_src + i),     s1 = __ldg(g_csr_src + i + 1);
        int s2 = __ldg(g_csr_src + i + 2), s3 = __ldg(g_csr_src + i + 3);
        float2 a0, c0, a1, c1, a2, c2, a3, c3;
        ldg_h4_f(T + (size_t)s0 * 128 + lane * 4, a0, c0);
        ldg_h4_f(T + (size_t)s1 * 128 + lane * 4, a1, c1);
        ldg_h4_f(T + (size_t)s2 * 128 + lane * 4, a2, c2);
        ldg_h4_f(T + (size_t)s3 * 128 + lane * 4, a3, c3);
        acc.x += (a0.x + a1.x) + (a2.x + a3.x);
        acc.y += (a0.y + a1.y) + (a2.y + a3.y);
        acc.z += (c0.x + c1.x) + (c2.x + c3.x);
        acc.w += (c0.y + c1.y) + (c2.y + c3.y);
    }
    for (; i < end; i++) {
        int s0 = __ldg(g_csr_src + i);
        float2 a0, c0;
        ldg_h4_f(T + (size_t)s0 * 128 + lane * 4, a0, c0);
        acc.x += a0.x; acc.y += a0.y; acc.z += c0.x; acc.w += c0.y;
    }
    float nd = g_norm_in[w];
    float4 bb = __ldg(((const float4*)b) + lane);
    float hx = fmaxf(fmaf(acc.x, nd, bb.x), 0.f);
    float hy = fmaxf(fmaf(acc.y, nd, bb.y), 0.f);
    float hz = fmaxf(fmaf(acc.z, nd, bb.z), 0.f);
    float hw = fmaxf(fmaf(acc.w, nd, bb.w), 0.f);
    __half2 o0 = __floats2half2_rn(hx, hy);
    __half2 o1 = __floats2half2_rn(hz, hw);
    uint2 u = make_uint2(*(unsigned*)&o0, *(unsigned*)&o1);
    ((uint2*)(out + (size_t)w * 128))[lane] = u;
}

// ===========================================================================
// gemm2 (HMMA): t2[row] = half( (h[row] @ W2) * norm_out[row] )   N=64
// ===========================================================================
__global__ __launch_bounds__(256)
void gemm2_mma_kernel(const __half* __restrict__ H,
                      const float* __restrict__ W,
                      __half* __restrict__ Y) {
    extern __shared__ __half hsm[];
    __half* A_s = hsm;                    // [128][ASTRIDE]
    __half* B_s = hsm + 128 * ASTRIDE;    // [128][BSTRIDE]

    const int tid = threadIdx.x;
    const int row0 = blockIdx.x * 128;

    for (int i = tid; i < 128 * 16; i += 256) {
        int k = i >> 4, c4 = i & 15;
        float4 v = __ldg(((const float4*)W) + i);
        __half2 h01 = __floats2half2_rn(v.x, v.y);
        __half2 h23 = __floats2half2_rn(v.z, v.w);
        uint2 u = make_uint2(*(unsigned*)&h01, *(unsigned*)&h23);
        *((uint2*)(B_s + k * BSTRIDE + c4 * 4)) = u;
    }
    for (int i = tid; i < 128 * 32; i += 256) {
        int r = i >> 5, c8 = i & 31;
        int row = row0 + r;
        uint2 u = (row < NN)
            ? __ldg(((const uint2*)(H + (size_t)row * 128)) + c8)
            : make_uint2(0u, 0u);
        *((uint2*)(A_s + r * ASTRIDE + c8 * 4)) = u;
    }
    __syncthreads();

    const int w = tid >> 5, lane = tid & 31;
    const int mrow = w * 16;

    float acc[8][4];
#pragma unroll
    for (int t = 0; t < 8; t++)
#pragma unroll
        for (int j = 0; j < 4; j++) acc[t][j] = 0.f;

#pragma unroll
    for (int ks = 0; ks < 8; ks++) {
        const int k0 = ks * 16;
        unsigned a0, a1, a2, a3;
        {
            const __half* pa = A_s + (mrow + (lane & 15)) * ASTRIDE
                             + k0 + (lane >> 4) * 8;
            unsigned addr = (unsigned)__cvta_generic_to_shared(pa);
            asm volatile("ldmatrix.sync.aligned.m8n8.x4.shared.b16 "
                         "{%0,%1,%2,%3}, [%4];"
                         : "=r"(a0), "=r"(a1), "=r"(a2), "=r"(a3) : "r"(addr));
        }
#pragma unroll
        for (int nt = 0; nt < 4; nt++) {
            unsigned b0, b1, b2, b3;
            const __half* pb = B_s + (k0 + (lane & 15)) * BSTRIDE
                             + nt * 16 + (lane >> 4) * 8;
            unsigned addr = (unsigned)__cvta_generic_to_shared(pb);
            asm volatile("ldmatrix.sync.aligned.m8n8.x4.trans.shared.b16 "
                         "{%0,%1,%2,%3}, [%4];"
                         : "=r"(b0), "=r"(b1), "=r"(b2), "=r"(b3) : "r"(addr));
            asm volatile("mma.sync.aligned.m16n8k16.row.col.f32.f16.f16.f32 "
                         "{%0,%1,%2,%3},{%4,%5,%6,%7},{%8,%9},{%0,%1,%2,%3};"
                         : "+f"(acc[nt*2][0]), "+f"(acc[nt*2][1]),
                           "+f"(acc[nt*2][2]), "+f"(acc[nt*2][3])
                         : "r"(a0), "r"(a1), "r"(a2), "r"(a3),
                           "r"(b0), "r"(b1));
            asm volatile("mma.sync.aligned.m16n8k16.row.col.f32.f16.f16.f32 "
                         "{%0,%1,%2,%3},{%4,%5,%6,%7},{%8,%9},{%0,%1,%2,%3};"
                         : "+f"(acc[nt*2+1][0]), "+f"(acc[nt*2+1][1]),
                           "+f"(acc[nt*2+1][2]), "+f"(acc[nt*2+1][3])
                         : "r"(a0), "r"(a1), "r"(a2), "r"(a3),
                           "r"(b2), "r"(b3));
        }
    }

    const int ra = row0 + mrow + (lane >> 2);
    const int rb = ra + 8;
    const float nsa = (ra < NN) ? __ldg(g_norm_out + ra) : 0.f;
    const float nsb = (rb < NN) ? __ldg(g_norm_out + rb) : 0.f;
    const int cbase = (lane & 3) * 2;
#pragma unroll
    for (int t = 0; t < 8; t++) {
        int c = t * 8 + cbase;
        if (ra < NN) {
            __half2 h = __floats2half2_rn(acc[t][0] * nsa, acc[t][1] * nsa);
            *((__half2*)(Y + (size_t)ra * 64 + c)) = h;
        }
        if (rb < NN) {
            __half2 h = __floats2half2_rn(acc[t][2] * nsb, acc[t][3] * nsb);
            *((__half2*)(Y + (size_t)rb * 64 + c)) = h;
        }
    }
}

// ===========================================================================
// Final gather: out[n] = norm_in[n] * sum t2[csr] + b2
// ===========================================================================
__global__ __launch_bounds__(256)
void gather64_kernel(const __half* __restrict__ T,
                     const float* __restrict__ b,
                     float* __restrict__ out) {
    int w = (blockIdx.x * blockDim.x + threadIdx.x) >> 5;
    int lane = threadIdx.x & 31;
    if (w >= NN) return;
    int beg = g_row_ptr[w], end = g_row_ptr[w + 1];
    float2 acc = make_float2(0.f, 0.f);
    int i = beg;
    for (; i + 3 < end; i += 4) {
        int s0 = __ldg(g_csr_src + i),     s1 = __ldg(g_csr_src + i + 1);
        int s2 = __ldg(g_csr_src + i + 2), s3 = __ldg(g_csr_src + i + 3);
        float2 f0 = ldg_h2_f(T + (size_t)s0 * 64 + lane * 2);
        float2 f1 = ldg_h2_f(T + (size_t)s1 * 64 + lane * 2);
        float2 f2 = ldg_h2_f(T + (size_t)s2 * 64 + lane * 2);
        float2 f3 = ldg_h2_f(T + (size_t)s3 * 64 + lane * 2);
        acc.x += (f0.x + f1.x) + (f2.x + f3.x);
        acc.y += (f0.y + f1.y) + (f2.y + f3.y);
    }
    for (; i < end; i++) {
        int s0 = __ldg(g_csr_src + i);
        float2 f0 = ldg_h2_f(T + (size_t)s0 * 64 + lane * 2);
        acc.x += f0.x; acc.y += f0.y;
    }
    float nd = g_norm_in[w];
    float2 bb = __ldg(((const float2*)b) + lane);
    float2 o;
    o.x = fmaf(acc.x, nd, bb.x);
    o.y = fmaf(acc.y, nd, bb.y);
    ((float2*)(out + (size_t)w * 64))[lane] = o;
}

// ===========================================================================
extern "C" void kernel_launch(void* const* d_in, const int* in_sizes, int n_in,
                              void* d_out, int out_size) {
    const float* x   = (const float*)d_in[0];
    const int*   src = (const int*)d_in[1];
    const int*   dst = (const int*)d_in[2];
    const float* W1  = (const float*)d_in[3];
    const float* b1  = (const float*)d_in[4];
    const float* W2  = (const float*)d_in[5];
    const float* b2  = (const float*)d_in[6];
    float* out = (float*)d_out;

    void *p_t1, *p_t2, *p_h;
    cudaGetSymbolAddress(&p_t1, g_t1);
    cudaGetSymbolAddress(&p_t2, g_t2);
    cudaGetSymbolAddress(&p_h,  g_h);

    size_t sm1 = (size_t)(2 * 128 * ASTRIDE) * sizeof(__half);   // ~68KB
    cudaFuncSetAttribute(gemm1_mma_kernel,
                         cudaFuncAttributeMaxDynamicSharedMemorySize, (int)sm1);
    size_t sm2 = (size_t)(128 * ASTRIDE + 128 * BSTRIDE) * sizeof(__half);
    cudaFuncSetAttribute(gemm2_mma_kernel,
                         cudaFuncAttributeMaxDynamicSharedMemorySize, (int)sm2);

    // One fused launch: zero + count + scan + norms + fill
    csr_build_fused<<<NB_F, TPB_F>>>((const int4*)src, (const int4*)dst);

    gemm1_mma_kernel<<<GB1M, 256, sm1>>>(x, W1, (__half*)p_t1);

    gather128_relu_kernel<<<(NN * 32 + 255) / 256, 256>>>(
        (const __half*)p_t1, b1, (__half*)p_h);

    gemm2_mma_kernel<<<GB1M, 256, sm2>>>(
        (const __half*)p_h, W2, (__half*)p_t2);

    gather64_kernel<<<(NN * 32 + 255) / 256, 256>>>(
        (const __half*)p_t2, b2, out);
}

// round 13
// speedup vs baseline: 1.0445x; 1.0445x over previous
#include <cuda_runtime.h>
#include <cuda_fp16.h>

#define NN 100000
#define NE 1600000
#define F_HID 128
#define F_CLS 64
#define NBLK_SCAN 98               // ceil(NN/1024)
#define GB1M ((NN + 127) / 128)    // 128-row mma tile blocks = 782
#define ASTRIDE 136                // halfs per smem row (272B, LDSM conflict-free)
#define BSTRIDE 72                 // halfs per smem row for 64-wide W2 (144B)
#define FILL_GRID ((NE / 4 + 255) / 256)   // 1563 edge blocks

// ---- scratch (device globals; no allocs allowed) ----
// g_cnt layout: [0,NN)=cnt_in, [NN,2NN)=cnt_out, [2NN,2NN+128)=scan_val,
//               [2NN+128,2NN+256)=scan_flag   (all zeroed by one memset)
__device__ int    g_cnt[2 * NN + 256];
__device__ int    g_row_ptr[NN + 1];
__device__ int    g_epos[NE];       // edge position within its dst row
__device__ int    g_csr_src[NE];
__device__ float  g_norm_in[NN];
__device__ float  g_norm_out[NN];
__device__ __half g_w2h[128 * F_CLS];   // fp16 copy of W2
__device__ __half g_t1[(size_t)NN * F_HID];
__device__ __half g_h [(size_t)NN * F_HID];
__device__ __half g_t2[(size_t)NN * F_CLS];

#define CNT_IN   (g_cnt)
#define CNT_OUT  (g_cnt + NN)
#define SCAN_VAL (g_cnt + 2 * NN)
#define SCAN_FLG (g_cnt + 2 * NN + 128)

// ---- fp16 vector load helpers ----
__device__ __forceinline__ void ldg_h4_f(const __half* p, float2& lo, float2& hi) {
    uint2 raw = __ldg((const uint2*)p);
    lo = __half22float2(*(const __half2*)&raw.x);
    hi = __half22float2(*(const __half2*)&raw.y);
}
__device__ __forceinline__ float2 ldg_h2_f(const __half* p) {
    unsigned int raw = __ldg((const unsigned int*)p);
    return __half22float2(*(const __half2*)&raw);
}

__device__ __forceinline__ int warp_incl_scan(int x, int lane) {
#pragma unroll
    for (int o = 1; o < 32; o <<= 1) {
        int y = __shfl_up_sync(0xffffffffu, x, o);
        if (lane >= o) x += y;
    }
    return x;
}

// ===========================================================================
// CSR build
// ===========================================================================
__global__ __launch_bounds__(256) void count_kernel(const int4* __restrict__ src4,
                                                    const int4* __restrict__ dst4) {
    int i = blockIdx.x * blockDim.x + threadIdx.x;   // NE/4 threads
    if (i < NE / 4) {
        int4 s = __ldg(src4 + i);
        int4 d = __ldg(dst4 + i);
        atomicAdd(&CNT_OUT[s.x], 1); atomicAdd(&CNT_OUT[s.y], 1);
        atomicAdd(&CNT_OUT[s.z], 1); atomicAdd(&CNT_OUT[s.w], 1);
        int4 p;
        p.x = atomicAdd(&CNT_IN[d.x], 1);
        p.y = atomicAdd(&CNT_IN[d.y], 1);
        p.z = atomicAdd(&CNT_IN[d.z], 1);
        p.w = atomicAdd(&CNT_IN[d.w], 1);
        ((int4*)g_epos)[i] = p;
    }
}

// Single-pass scan with aggregate lookback (98 resident blocks).
__global__ __launch_bounds__(1024) void scan_onepass_kernel() {
    __shared__ int ws[32];
    __shared__ int s_base;
    int t = threadIdx.x, lane = t & 31, wid = t >> 5;
    int bid = blockIdx.x;

    int i = bid * 1024 + t;
    int v = (i < NN) ? CNT_IN[i] : 0;
    int x = warp_incl_scan(v, lane);
    if (lane == 31) ws[wid] = x;
    __syncthreads();
    if (wid == 0) ws[lane] = warp_incl_scan(ws[lane], lane);
    __syncthreads();
    int incl = x + (wid ? ws[wid - 1] : 0);
    int total = ws[31];

    if (t == 0) {
        SCAN_VAL[bid] = total;
        __threadfence();
        ((volatile int*)SCAN_FLG)[bid] = 1;
    }
    if (wid == 0) {
        int p = 0;
        for (int j = lane; j < bid; j += 32) {
            while (((volatile int*)SCAN_FLG)[j] == 0) { }
            p += ((volatile int*)SCAN_VAL)[j];
        }
        p = __reduce_add_sync(0xffffffffu, p);
        if (lane == 0) s_base = p;
    }
    __syncthreads();

    if (i < NN) {
        g_row_ptr[i] = incl - v + s_base;
        g_norm_in[i]  = rsqrtf(fmaxf((float)v, 1.0f));
        g_norm_out[i] = rsqrtf(fmaxf((float)CNT_OUT[i], 1.0f));
    }
    if (bid == 0 && t == 0) g_row_ptr[NN] = NE;
}

// fill: pure scatter, no atomics; one extra tail block converts W2 -> fp16.
__global__ __launch_bounds__(256) void fill_kernel(const int4* __restrict__ src4,
                                                   const int4* __restrict__ dst4,
                                                   const float* __restrict__ W2) {
    if (blockIdx.x == FILL_GRID) {   // tail block: W2 fp32 -> fp16 (8192 elems)
        int t = threadIdx.x;
        for (int i = t; i < 128 * F_CLS / 4; i += 256) {
            float4 v = __ldg(((const float4*)W2) + i);
            __half2 h01 = __floats2half2_rn(v.x, v.y);
            __half2 h23 = __floats2half2_rn(v.z, v.w);
            uint2 u = make_uint2(*(unsigned*)&h01, *(unsigned*)&h23);
            ((uint2*)g_w2h)[i] = u;
        }
        return;
    }
    int i = blockIdx.x * blockDim.x + threadIdx.x;
    if (i < NE / 4) {
        int4 s = __ldg(src4 + i);
        int4 d = __ldg(dst4 + i);
        int4 p = ((const int4*)g_epos)[i];
        g_csr_src[__ldg(g_row_ptr + d.x) + p.x] = s.x;
        g_csr_src[__ldg(g_row_ptr + d.y) + p.y] = s.y;
        g_csr_src[__ldg(g_row_ptr + d.z) + p.z] = s.z;
        g_csr_src[__ldg(g_row_ptr + d.w) + p.w] = s.w;
    }
}

// ===========================================================================
// gemm1 (HMMA fp16, fp32 accum):
//   t1[row] = half( (x[row] @ W1) * norm_out[row] )
// ===========================================================================
__global__ __launch_bounds__(256)
void gemm1_mma_kernel(const float* __restrict__ X,
                      const float* __restrict__ W,
                      __half* __restrict__ Y) {
    extern __shared__ __half hsm[];
    __half* A_s = hsm;                    // [128][ASTRIDE]
    __half* B_s = hsm + 128 * ASTRIDE;    // [128][ASTRIDE]

    const int tid = threadIdx.x;
    const int row0 = blockIdx.x * 128;

    for (int i = tid; i < 128 * 32; i += 256) {
        int k = i >> 5, c4 = i & 31;
        float4 v = __ldg(((const float4*)W) + i);
        __half2 h01 = __floats2half2_rn(v.x, v.y);
        __half2 h23 = __floats2half2_rn(v.z, v.w);
        uint2 u = make_uint2(*(unsigned*)&h01, *(unsigned*)&h23);
        *((uint2*)(B_s + k * ASTRIDE + c4 * 4)) = u;
    }
    for (int i = tid; i < 128 * 32; i += 256) {
        int r = i >> 5, c4 = i & 31;
        int row = row0 + r;
        float4 v = (row < NN)
            ? __ldg(((const float4*)(X + (size_t)row * 128)) + c4)
            : make_float4(0.f, 0.f, 0.f, 0.f);
        __half2 h01 = __floats2half2_rn(v.x, v.y);
        __half2 h23 = __floats2half2_rn(v.z, v.w);
        uint2 u = make_uint2(*(unsigned*)&h01, *(unsigned*)&h23);
        *((uint2*)(A_s + r * ASTRIDE + c4 * 4)) = u;
    }
    __syncthreads();

    const int w = tid >> 5, lane = tid & 31;
    const int mrow = w * 16;

    float acc[16][4];
#pragma unroll
    for (int t = 0; t < 16; t++)
#pragma unroll
        for (int j = 0; j < 4; j++) acc[t][j] = 0.f;

#pragma unroll
    for (int ks = 0; ks < 8; ks++) {
        const int k0 = ks * 16;
        unsigned a0, a1, a2, a3;
        {
            const __half* pa = A_s + (mrow + (lane & 15)) * ASTRIDE
                             + k0 + (lane >> 4) * 8;
            unsigned addr = (unsigned)__cvta_generic_to_shared(pa);
            asm volatile("ldmatrix.sync.aligned.m8n8.x4.shared.b16 "
                         "{%0,%1,%2,%3}, [%4];"
                         : "=r"(a0), "=r"(a1), "=r"(a2), "=r"(a3) : "r"(addr));
        }
#pragma unroll
        for (int nt = 0; nt < 8; nt++) {
            unsigned b0, b1, b2, b3;
            const __half* pb = B_s + (k0 + (lane & 15)) * ASTRIDE
                             + nt * 16 + (lane >> 4) * 8;
            unsigned addr = (unsigned)__cvta_generic_to_shared(pb);
            asm volatile("ldmatrix.sync.aligned.m8n8.x4.trans.shared.b16 "
                         "{%0,%1,%2,%3}, [%4];"
                         : "=r"(b0), "=r"(b1), "=r"(b2), "=r"(b3) : "r"(addr));
            asm volatile("mma.sync.aligned.m16n8k16.row.col.f32.f16.f16.f32 "
                         "{%0,%1,%2,%3},{%4,%5,%6,%7},{%8,%9},{%0,%1,%2,%3};"
                         : "+f"(acc[nt*2][0]), "+f"(acc[nt*2][1]),
                           "+f"(acc[nt*2][2]), "+f"(acc[nt*2][3])
                         : "r"(a0), "r"(a1), "r"(a2), "r"(a3),
                           "r"(b0), "r"(b1));
            asm volatile("mma.sync.aligned.m16n8k16.row.col.f32.f16.f16.f32 "
                         "{%0,%1,%2,%3},{%4,%5,%6,%7},{%8,%9},{%0,%1,%2,%3};"
                         : "+f"(acc[nt*2+1][0]), "+f"(acc[nt*2+1][1]),
                           "+f"(acc[nt*2+1][2]), "+f"(acc[nt*2+1][3])
                         : "r"(a0), "r"(a1), "r"(a2), "r"(a3),
                           "r"(b2), "r"(b3));
        }
    }

    const int ra = row0 + mrow + (lane >> 2);
    const int rb = ra + 8;
    const float nsa = (ra < NN) ? __ldg(g_norm_out + ra) : 0.f;
    const float nsb = (rb < NN) ? __ldg(g_norm_out + rb) : 0.f;
    const int cbase = (lane & 3) * 2;
#pragma unroll
    for (int t = 0; t < 16; t++) {
        int c = t * 8 + cbase;
        if (ra < NN) {
            __half2 h = __floats2half2_rn(acc[t][0] * nsa, acc[t][1] * nsa);
            *((__half2*)(Y + (size_t)ra * 128 + c)) = h;
        }
        if (rb < NN) {
            __half2 h = __floats2half2_rn(acc[t][2] * nsb, acc[t][3] * nsb);
            *((__half2*)(Y + (size_t)rb * 128 + c)) = h;
        }
    }
}

// ===========================================================================
// gather128+relu: h[n] = half( relu(norm_in[n]*sum t1[csr] + b1) )
// ===========================================================================
__global__ __launch_bounds__(256)
void gather128_relu_kernel(const __half* __restrict__ T,
                           const float* __restrict__ b,
                           __half* __restrict__ out) {
    int w = (blockIdx.x * blockDim.x + threadIdx.x) >> 5;
    int lane = threadIdx.x & 31;
    if (w >= NN) return;
    int beg = g_row_ptr[w], end = g_row_ptr[w + 1];
    float4 acc = make_float4(0.f, 0.f, 0.f, 0.f);
    int i = beg;
    for (; i + 3 < end; i += 4) {
        int s0 = __ldg(g_csr_src + i),     s1 = __ldg(g_csr_src + i + 1);
        int s2 = __ldg(g_csr_src + i + 2), s3 = __ldg(g_csr_src + i + 3);
        float2 a0, c0, a1, c1, a2, c2, a3, c3;
        ldg_h4_f(T + (size_t)s0 * 128 + lane * 4, a0, c0);
        ldg_h4_f(T + (size_t)s1 * 128 + lane * 4, a1, c1);
        ldg_h4_f(T + (size_t)s2 * 128 + lane * 4, a2, c2);
        ldg_h4_f(T + (size_t)s3 * 128 + lane * 4, a3, c3);
        acc.x += (a0.x + a1.x) + (a2.x + a3.x);
        acc.y += (a0.y + a1.y) + (a2.y + a3.y);
        acc.z += (c0.x + c1.x) + (c2.x + c3.x);
        acc.w += (c0.y + c1.y) + (c2.y + c3.y);
    }
    for (; i < end; i++) {
        int s0 = __ldg(g_csr_src + i);
        float2 a0, c0;
        ldg_h4_f(T + (size_t)s0 * 128 + lane * 4, a0, c0);
        acc.x += a0.x; acc.y += a0.y; acc.z += c0.x; acc.w += c0.y;
    }
    float nd = g_norm_in[w];
    float4 bb = __ldg(((const float4*)b) + lane);
    float hx = fmaxf(fmaf(acc.x, nd, bb.x), 0.f);
    float hy = fmaxf(fmaf(acc.y, nd, bb.y), 0.f);
    float hz = fmaxf(fmaf(acc.z, nd, bb.z), 0.f);
    float hw = fmaxf(fmaf(acc.w, nd, bb.w), 0.f);
    __half2 o0 = __floats2half2_rn(hx, hy);
    __half2 o1 = __floats2half2_rn(hz, hw);
    uint2 u = make_uint2(*(unsigned*)&o0, *(unsigned*)&o1);
    ((uint2*)(out + (size_t)w * 128))[lane] = u;
}

// ===========================================================================
// gemm2 (HMMA): t2[row] = half( (h[row] @ W2) * norm_out[row] )   N=64
// W2 pre-converted to fp16 (g_w2h) -> less traffic, less smem, more blocks/SM.
// ===========================================================================
__global__ __launch_bounds__(256)
void gemm2_mma_kernel(const __half* __restrict__ H,
                      __half* __restrict__ Y) {
    extern __shared__ __half hsm[];
    __half* A_s = hsm;                    // [128][ASTRIDE]  ~34.8KB
    __half* B_s = hsm + 128 * ASTRIDE;    // [128][BSTRIDE]  ~9.2KB

    const int tid = threadIdx.x;
    const int row0 = blockIdx.x * 128;

    // W2 fp16 -> B_s (2048 uint2)
    for (int i = tid; i < 128 * 16; i += 256) {
        int k = i >> 4, c4 = i & 15;
        uint2 u = __ldg(((const uint2*)g_w2h) + i);
        *((uint2*)(B_s + k * BSTRIDE + c4 * 4)) = u;
    }
    // h tile fp16 -> A_s: 128 rows x 32 uint2
    for (int i = tid; i < 128 * 32; i += 256) {
        int r = i >> 5, c8 = i & 31;
        int row = row0 + r;
        uint2 u = (row < NN)
            ? __ldg(((const uint2*)(H + (size_t)row * 128)) + c8)
            : make_uint2(0u, 0u);
        *((uint2*)(A_s + r * ASTRIDE + c8 * 4)) = u;
    }
    __syncthreads();

    const int w = tid >> 5, lane = tid & 31;
    const int mrow = w * 16;

    float acc[8][4];
#pragma unroll
    for (int t = 0; t < 8; t++)
#pragma unroll
        for (int j = 0; j < 4; j++) acc[t][j] = 0.f;

#pragma unroll
    for (int ks = 0; ks < 8; ks++) {
        const int k0 = ks * 16;
        unsigned a0, a1, a2, a3;
        {
            const __half* pa = A_s + (mrow + (lane & 15)) * ASTRIDE
                             + k0 + (lane >> 4) * 8;
            unsigned addr = (unsigned)__cvta_generic_to_shared(pa);
            asm volatile("ldmatrix.sync.aligned.m8n8.x4.shared.b16 "
                         "{%0,%1,%2,%3}, [%4];"
                         : "=r"(a0), "=r"(a1), "=r"(a2), "=r"(a3) : "r"(addr));
        }
#pragma unroll
        for (int nt = 0; nt < 4; nt++) {
            unsigned b0, b1, b2, b3;
            const __half* pb = B_s + (k0 + (lane & 15)) * BSTRIDE
                             + nt * 16 + (lane >> 4) * 8;
            unsigned addr = (unsigned)__cvta_generic_to_shared(pb);
            asm volatile("ldmatrix.sync.aligned.m8n8.x4.trans.shared.b16 "
                         "{%0,%1,%2,%3}, [%4];"
                         : "=r"(b0), "=r"(b1), "=r"(b2), "=r"(b3) : "r"(addr));
            asm volatile("mma.sync.aligned.m16n8k16.row.col.f32.f16.f16.f32 "
                         "{%0,%1,%2,%3},{%4,%5,%6,%7},{%8,%9},{%0,%1,%2,%3};"
                         : "+f"(acc[nt*2][0]), "+f"(acc[nt*2][1]),
                           "+f"(acc[nt*2][2]), "+f"(acc[nt*2][3])
                         : "r"(a0), "r"(a1), "r"(a2), "r"(a3),
                           "r"(b0), "r"(b1));
            asm volatile("mma.sync.aligned.m16n8k16.row.col.f32.f16.f16.f32 "
                         "{%0,%1,%2,%3},{%4,%5,%6,%7},{%8,%9},{%0,%1,%2,%3};"
                         : "+f"(acc[nt*2+1][0]), "+f"(acc[nt*2+1][1]),
                           "+f"(acc[nt*2+1][2]), "+f"(acc[nt*2+1][3])
                         : "r"(a0), "r"(a1), "r"(a2), "r"(a3),
                           "r"(b2), "r"(b3));
        }
    }

    const int ra = row0 + mrow + (lane >> 2);
    const int rb = ra + 8;
    const float nsa = (ra < NN) ? __ldg(g_norm_out + ra) : 0.f;
    const float nsb = (rb < NN) ? __ldg(g_norm_out + rb) : 0.f;
    const int cbase = (lane & 3) * 2;
#pragma unroll
    for (int t = 0; t < 8; t++) {
        int c = t * 8 + cbase;
        if (ra < NN) {
            __half2 h = __floats2half2_rn(acc[t][0] * nsa, acc[t][1] * nsa);
            *((__half2*)(Y + (size_t)ra * 64 + c)) = h;
        }
        if (rb < NN) {
            __half2 h = __floats2half2_rn(acc[t][2] * nsb, acc[t][3] * nsb);
            *((__half2*)(Y + (size_t)rb * 64 + c)) = h;
        }
    }
}

// ===========================================================================
// Final gather: out[n] = norm_in[n] * sum t2[csr] + b2
// ===========================================================================
__global__ __launch_bounds__(256)
void gather64_kernel(const __half* __restrict__ T,
                     const float* __restrict__ b,
                     float* __restrict__ out) {
    int w = (blockIdx.x * blockDim.x + threadIdx.x) >> 5;
    int lane = threadIdx.x & 31;
    if (w >= NN) return;
    int beg = g_row_ptr[w], end = g_row_ptr[w + 1];
    float2 acc = make_float2(0.f, 0.f);
    int i = beg;
    for (; i + 3 < end; i += 4) {
        int s0 = __ldg(g_csr_src + i),     s1 = __ldg(g_csr_src + i + 1);
        int s2 = __ldg(g_csr_src + i + 2), s3 = __ldg(g_csr_src + i + 3);
        float2 f0 = ldg_h2_f(T + (size_t)s0 * 64 + lane * 2);
        float2 f1 = ldg_h2_f(T + (size_t)s1 * 64 + lane * 2);
        float2 f2 = ldg_h2_f(T + (size_t)s2 * 64 + lane * 2);
        float2 f3 = ldg_h2_f(T + (size_t)s3 * 64 + lane * 2);
        acc.x += (f0.x + f1.x) + (f2.x + f3.x);
        acc.y += (f0.y + f1.y) + (f2.y + f3.y);
    }
    for (; i < end; i++) {
        int s0 = __ldg(g_csr_src + i);
        float2 f0 = ldg_h2_f(T + (size_t)s0 * 64 + lane * 2);
        acc.x += f0.x; acc.y += f0.y;
    }
    float nd = g_norm_in[w];
    float2 bb = __ldg(((const float2*)b) + lane);
    float2 o;
    o.x = fmaf(acc.x, nd, bb.x);
    o.y = fmaf(acc.y, nd, bb.y);
    ((float2*)(out + (size_t)w * 64))[lane] = o;
}

// ===========================================================================
extern "C" void kernel_launch(void* const* d_in, const int* in_sizes, int n_in,
                              void* d_out, int out_size) {
    const float* x   = (const float*)d_in[0];
    const int*   src = (const int*)d_in[1];
    const int*   dst = (const int*)d_in[2];
    const float* W1  = (const float*)d_in[3];
    const float* b1  = (const float*)d_in[4];
    const float* W2  = (const float*)d_in[5];
    const float* b2  = (const float*)d_in[6];
    float* out = (float*)d_out;

    void *p_t1, *p_t2, *p_h, *p_cnt;
    cudaGetSymbolAddress(&p_t1, g_t1);
    cudaGetSymbolAddress(&p_t2, g_t2);
    cudaGetSymbolAddress(&p_h,  g_h);
    cudaGetSymbolAddress(&p_cnt, g_cnt);

    size_t sm1 = (size_t)(2 * 128 * ASTRIDE) * sizeof(__half);   // ~68KB
    cudaFuncSetAttribute(gemm1_mma_kernel,
                         cudaFuncAttributeMaxDynamicSharedMemorySize, (int)sm1);
    size_t sm2 = (size_t)(128 * ASTRIDE + 128 * BSTRIDE) * sizeof(__half); // ~44KB
    cudaFuncSetAttribute(gemm2_mma_kernel,
                         cudaFuncAttributeMaxDynamicSharedMemorySize, (int)sm2);

    cudaMemsetAsync(p_cnt, 0, (2 * NN + 256) * sizeof(int));
    count_kernel<<<(NE / 4 + 255) / 256, 256>>>((const int4*)src, (const int4*)dst);
    scan_onepass_kernel<<<NBLK_SCAN, 1024>>>();
    fill_kernel<<<FILL_GRID + 1, 256>>>((const int4*)src, (const int4*)dst, W2);

    gemm1_mma_kernel<<<GB1M, 256, sm1>>>(x, W1, (__half*)p_t1);

    gather128_relu_kernel<<<(NN * 32 + 255) / 256, 256>>>(
        (const __half*)p_t1, b1, (__half*)p_h);

    gemm2_mma_kernel<<<GB1M, 256, sm2>>>((const __half*)p_h, (__half*)p_t2);

    gather64_kernel<<<(NN * 32 + 255) / 256, 256>>>(
        (const __half*)p_t2, b2, out);
}